// round 1
// baseline (speedup 1.0000x reference)
#include <cuda_runtime.h>
#include <math_constants.h>

// Problem constants (fixed shapes from reference)
#define SEQ   4096
#define DMODEL 1024
#define NH    16
#define DH    64
#define WIN   256

// Scratch (allocation-free rule: __device__ globals)
__device__ float g_q[SEQ * DMODEL];
__device__ float g_k[SEQ * DMODEL];
__device__ float g_v[SEQ * DMODEL];
__device__ float g_attn[SEQ * DMODEL];

// ---------------------------------------------------------------------------
// Tiled SGEMM: C[M,N] = A[M,K] @ B[K,N], all row-major.
// BM=BN=128, BK=8, 256 threads, 8x8 microtile per thread.
// Requires M%128==0, N%128==0, K%8==0 (true here: 4096/1024/1024).
// ---------------------------------------------------------------------------
__global__ void __launch_bounds__(256, 2) sgemm_kernel(
    const float* __restrict__ A, const float* __restrict__ B,
    float* __restrict__ C, int M, int N, int K)
{
    __shared__ float As[8][128];
    __shared__ float Bs[8][128];

    const int tid = threadIdx.x;
    const int tx  = tid & 15;        // 0..15 -> N microtile
    const int ty  = tid >> 4;        // 0..15 -> M microtile

    const int row0 = blockIdx.y * 128;
    const int col0 = blockIdx.x * 128;

    const int a_row = tid >> 1;          // 0..127
    const int a_col = (tid & 1) * 4;     // 0 or 4
    const int b_row = tid >> 5;          // 0..7
    const int b_col = (tid & 31) * 4;    // 0..124

    float acc[8][8];
#pragma unroll
    for (int i = 0; i < 8; i++)
#pragma unroll
        for (int j = 0; j < 8; j++) acc[i][j] = 0.0f;

    for (int kt = 0; kt < K; kt += 8) {
        // Load A tile (transposed into As[k][m]) and B tile
        float4 av = *(const float4*)(A + (size_t)(row0 + a_row) * K + kt + a_col);
        As[a_col + 0][a_row] = av.x;
        As[a_col + 1][a_row] = av.y;
        As[a_col + 2][a_row] = av.z;
        As[a_col + 3][a_row] = av.w;
        *(float4*)(&Bs[b_row][b_col]) =
            *(const float4*)(B + (size_t)(kt + b_row) * N + col0 + b_col);
        __syncthreads();

#pragma unroll
        for (int k = 0; k < 8; k++) {
            float a[8], b[8];
#pragma unroll
            for (int i = 0; i < 8; i++) a[i] = As[k][ty * 8 + i];
#pragma unroll
            for (int j = 0; j < 8; j++) b[j] = Bs[k][tx * 8 + j];
#pragma unroll
            for (int i = 0; i < 8; i++)
#pragma unroll
                for (int j = 0; j < 8; j++)
                    acc[i][j] = fmaf(a[i], b[j], acc[i][j]);
        }
        __syncthreads();
    }

#pragma unroll
    for (int i = 0; i < 8; i++) {
        float* crow = C + (size_t)(row0 + ty * 8 + i) * N + col0 + tx * 8;
        float4 v0 = make_float4(acc[i][0], acc[i][1], acc[i][2], acc[i][3]);
        float4 v1 = make_float4(acc[i][4], acc[i][5], acc[i][6], acc[i][7]);
        *(float4*)(crow + 0) = v0;
        *(float4*)(crow + 4) = v1;
    }
}

// ---------------------------------------------------------------------------
// Sliding-window flash attention, fp32.
// Grid: (SEQ/32, NH). Block: 128 threads = 32 queries x 4 sub-threads.
// Each sub-thread owns 16 of the 64 head dims (q regs + acc regs).
// Keys processed in chunks of 32 staged through smem (K + V tiles).
// Online softmax with rescale-on-new-max.
// ---------------------------------------------------------------------------
__global__ void __launch_bounds__(128) attn_kernel()
{
    __shared__ float ks[32][64];
    __shared__ float vs[32][64];

    const int h   = blockIdx.y;
    const int t0  = blockIdx.x * 32;        // first query of tile
    const int tid = threadIdx.x;
    const int qi  = tid >> 2;               // 0..31 query within tile
    const int sub = tid & 3;                // 0..3  dim group
    const int i   = t0 + qi;                // global query index

    const float scale = 0.125f;             // 1/sqrt(64)
    float qreg[16];
    const float* qptr = g_q + (size_t)i * DMODEL + h * DH + sub * 16;
#pragma unroll
    for (int t = 0; t < 16; t++) qreg[t] = qptr[t] * scale;

    float m = -CUDART_INF_F;
    float l = 0.0f;
    float acc[16];
#pragma unroll
    for (int t = 0; t < 16; t++) acc[t] = 0.0f;

    const int jstart = max(0, t0 - WIN);    // multiple of 32

    for (int jc = jstart; jc <= t0; jc += 32) {
        // Stage K and V chunk: 32 rows x 64 floats each.
        // 512 float4 per array; 4 per thread, coalesced along rows.
#pragma unroll
        for (int u = 0; u < 4; u++) {
            int idx = tid + u * 128;        // 0..511
            int r   = idx >> 4;             // row 0..31
            int c4  = (idx & 15) * 4;       // col 0..60
            size_t goff = (size_t)(jc + r) * DMODEL + h * DH + c4;
            *(float4*)(&ks[r][c4]) = *(const float4*)(g_k + goff);
            *(float4*)(&vs[r][c4]) = *(const float4*)(g_v + goff);
        }
        __syncthreads();

        for (int jj = 0; jj < 32; jj++) {
            const int j = jc + jj;
            float partial = 0.0f;
#pragma unroll
            for (int t = 0; t < 16; t++)
                partial = fmaf(qreg[t], ks[jj][sub * 16 + t], partial);
            // reduce across the 4 sub-threads of this query
            partial += __shfl_xor_sync(0xffffffffu, partial, 1);
            partial += __shfl_xor_sync(0xffffffffu, partial, 2);

            const bool valid = (j <= i) && (j >= i - WIN);
            if (valid) {
                float s = partial;
                if (s > m) {
                    float c = __expf(m - s);
                    l *= c;
#pragma unroll
                    for (int t = 0; t < 16; t++) acc[t] *= c;
                    m = s;
                }
                float p = __expf(s - m);
                l += p;
#pragma unroll
                for (int t = 0; t < 16; t++)
                    acc[t] = fmaf(p, vs[jj][sub * 16 + t], acc[t]);
            }
        }
        __syncthreads();
    }

    const float inv = 1.0f / l;
    float* optr = g_attn + (size_t)i * DMODEL + h * DH + sub * 16;
#pragma unroll
    for (int t = 0; t < 16; t++) optr[t] = acc[t] * inv;
}

// ---------------------------------------------------------------------------
// Launch: Q/K/V projections -> attention -> output projection
// ---------------------------------------------------------------------------
extern "C" void kernel_launch(void* const* d_in, const int* in_sizes, int n_in,
                              void* d_out, int out_size)
{
    const float* x  = (const float*)d_in[0];
    const float* Wq = (const float*)d_in[1];
    const float* Wk = (const float*)d_in[2];
    const float* Wv = (const float*)d_in[3];
    const float* Wo = (const float*)d_in[4];
    float* out = (float*)d_out;

    float *q, *k, *v, *attn;
    cudaGetSymbolAddress((void**)&q,    g_q);
    cudaGetSymbolAddress((void**)&k,    g_k);
    cudaGetSymbolAddress((void**)&v,    g_v);
    cudaGetSymbolAddress((void**)&attn, g_attn);

    dim3 ggrid(DMODEL / 128, SEQ / 128);   // (8, 32)
    sgemm_kernel<<<ggrid, 256>>>(x, Wq, q, SEQ, DMODEL, DMODEL);
    sgemm_kernel<<<ggrid, 256>>>(x, Wk, k, SEQ, DMODEL, DMODEL);
    sgemm_kernel<<<ggrid, 256>>>(x, Wv, v, SEQ, DMODEL, DMODEL);

    attn_kernel<<<dim3(SEQ / 32, NH), 128>>>();

    sgemm_kernel<<<ggrid, 256>>>(attn, Wo, out, SEQ, DMODEL, DMODEL);
}

// round 3
// speedup vs baseline: 3.2318x; 3.2318x over previous
#include <cuda_runtime.h>
#include <cuda_bf16.h>

#define SEQ 4096
#define DM  1024
#define NH  16
#define DH  64
#define WIN 256

// Scratch (allocation-free rule)
__device__ float g_q[SEQ * DM];
__device__ float g_k[SEQ * DM];
__device__ float g_v[SEQ * DM];
__device__ float g_attn[SEQ * DM];

// ---------------------------------------------------------------------------
// Helpers
// ---------------------------------------------------------------------------
__device__ __forceinline__ unsigned f2tf(float f) {
    unsigned r;
    asm("cvt.rna.tf32.f32 %0, %1;" : "=r"(r) : "f"(f));
    return r;
}

// Split (x,y) into bf16 hi-pair and lo-pair (packed 2xbf16 in u32, low=first).
__device__ __forceinline__ void split_pair(float x, float y, unsigned& hi, unsigned& lo) {
    __nv_bfloat16 hx = __float2bfloat16(x);
    __nv_bfloat16 hy = __float2bfloat16(y);
    __nv_bfloat16 lx = __float2bfloat16(x - __bfloat162float(hx));
    __nv_bfloat16 ly = __float2bfloat16(y - __bfloat162float(hy));
    __nv_bfloat162 h; h.x = hx; h.y = hy;
    __nv_bfloat162 l; l.x = lx; l.y = ly;
    hi = *(unsigned*)&h;
    lo = *(unsigned*)&l;
}

// m16n8k16 bf16 MMA, f32 accumulate (in-place)
__device__ __forceinline__ void mma_bf(float* c, const unsigned* a, const unsigned* b) {
    asm volatile(
        "mma.sync.aligned.m16n8k16.row.col.f32.bf16.bf16.f32 "
        "{%0,%1,%2,%3},{%4,%5,%6,%7},{%8,%9},{%0,%1,%2,%3};"
        : "+f"(c[0]), "+f"(c[1]), "+f"(c[2]), "+f"(c[3])
        : "r"(a[0]), "r"(a[1]), "r"(a[2]), "r"(a[3]), "r"(b[0]), "r"(b[1]));
}

// m16n8k8 tf32 MMA, f32 accumulate (in-place)
__device__ __forceinline__ void mma_tf(float* c, const unsigned* a, const unsigned* b) {
    asm volatile(
        "mma.sync.aligned.m16n8k8.row.col.f32.tf32.tf32.f32 "
        "{%0,%1,%2,%3},{%4,%5,%6,%7},{%8,%9},{%0,%1,%2,%3};"
        : "+f"(c[0]), "+f"(c[1]), "+f"(c[2]), "+f"(c[3])
        : "r"(a[0]), "r"(a[1]), "r"(a[2]), "r"(a[3]), "r"(b[0]), "r"(b[1]));
}

// ---------------------------------------------------------------------------
// bf16x2-split GEMM: C[M,N] = A[M,K] @ B[K,N], fp32 in/out, ~1e-5 rel err.
// BM=BN=128, BK=16, 256 threads (8 warps, 2x4), warp tile 64x32,
// mma m16n8k16 x (4 mtiles x 4 ntiles) x 3 passes.
// Smem: pairs along K. Ah/Al: [kp][m] (transposed), Bh/Bl: [kp][n].
// Stride 136 (== 8 mod 32) -> conflict-free fragment reads.
// ---------------------------------------------------------------------------
__global__ void __launch_bounds__(256) gemm_bf16x2(
    const float* __restrict__ A, const float* __restrict__ B,
    float* __restrict__ C, int M, int N, int K)
{
    __shared__ unsigned Ah[8][136], Al[8][136], Bh[8][136], Bl[8][136];

    const int tid = threadIdx.x;
    const int lane = tid & 31, warp = tid >> 5;
    const int g = lane >> 2, tig = lane & 3;
    const int wm = (warp >> 2) * 64, wn = (warp & 3) * 32;
    const int row0 = blockIdx.y * 128, col0 = blockIdx.x * 128;

    float acc[4][4][4];
#pragma unroll
    for (int a = 0; a < 4; a++)
#pragma unroll
        for (int b = 0; b < 4; b++)
#pragma unroll
            for (int c = 0; c < 4; c++) acc[a][b][c] = 0.0f;

    for (int kt = 0; kt < K; kt += 16) {
        // Load A tile 128x16 (512 float4, 2 per thread), transpose into [kp][m]
#pragma unroll
        for (int u = 0; u < 2; u++) {
            int idx = tid + u * 256;
            int r = idx >> 2, kp = (idx & 3) * 2;  // kp: pair index 0,2,4,6
            float4 v = *(const float4*)(A + (size_t)(row0 + r) * K + kt + kp * 2);
            unsigned h0, l0, h1, l1;
            split_pair(v.x, v.y, h0, l0);
            split_pair(v.z, v.w, h1, l1);
            Ah[kp][r] = h0; Al[kp][r] = l0;
            Ah[kp + 1][r] = h1; Al[kp + 1][r] = l1;
        }
        // Load B tile 16x128: pairs vertical (k-adjacent rows), 1 task/thread
        {
            int pr = tid >> 5, c4 = (tid & 31) * 4;
            const float* bp = B + (size_t)(kt + pr * 2) * N + col0 + c4;
            float4 r0 = *(const float4*)bp;
            float4 r1 = *(const float4*)(bp + N);
            unsigned h, l;
            split_pair(r0.x, r1.x, h, l); Bh[pr][c4 + 0] = h; Bl[pr][c4 + 0] = l;
            split_pair(r0.y, r1.y, h, l); Bh[pr][c4 + 1] = h; Bl[pr][c4 + 1] = l;
            split_pair(r0.z, r1.z, h, l); Bh[pr][c4 + 2] = h; Bl[pr][c4 + 2] = l;
            split_pair(r0.w, r1.w, h, l); Bh[pr][c4 + 3] = h; Bl[pr][c4 + 3] = l;
        }
        __syncthreads();

        unsigned bh[4][2], bl[4][2];
#pragma unroll
        for (int nt = 0; nt < 4; nt++) {
            int n = wn + nt * 8 + g;
            bh[nt][0] = Bh[tig][n];     bh[nt][1] = Bh[tig + 4][n];
            bl[nt][0] = Bl[tig][n];     bl[nt][1] = Bl[tig + 4][n];
        }
#pragma unroll
        for (int mt = 0; mt < 4; mt++) {
            int m = wm + mt * 16 + g;
            unsigned ah[4], al[4];
            ah[0] = Ah[tig][m];     ah[1] = Ah[tig][m + 8];
            ah[2] = Ah[tig + 4][m]; ah[3] = Ah[tig + 4][m + 8];
            al[0] = Al[tig][m];     al[1] = Al[tig][m + 8];
            al[2] = Al[tig + 4][m]; al[3] = Al[tig + 4][m + 8];
#pragma unroll
            for (int nt = 0; nt < 4; nt++) {
                mma_bf(acc[mt][nt], ah, bh[nt]);
                mma_bf(acc[mt][nt], ah, bl[nt]);
                mma_bf(acc[mt][nt], al, bh[nt]);
            }
        }
        __syncthreads();
    }

    // Epilogue: C fragment rows g/g+8, cols 2*tig, 2*tig+1
#pragma unroll
    for (int mt = 0; mt < 4; mt++) {
#pragma unroll
        for (int nt = 0; nt < 4; nt++) {
            int r = row0 + wm + mt * 16 + g;
            int cc = col0 + wn + nt * 8 + 2 * tig;
            *(float2*)(C + (size_t)r * N + cc) =
                make_float2(acc[mt][nt][0], acc[mt][nt][1]);
            *(float2*)(C + (size_t)(r + 8) * N + cc) =
                make_float2(acc[mt][nt][2], acc[mt][nt][3]);
        }
    }
}

// ---------------------------------------------------------------------------
// Warp-tiled flash attention, sliding window causal.
// Grid (SEQ/64, NH), 128 threads (4 warps). Warp w owns 16 query rows.
// QK^T: bf16x2 (3 mma), softmax fp32, P@V: tf32 (P through smem).
// Key chunks of 32, iterated DESCENDING so the first computed chunk per warp
// contains its diagonal (masking with -1e30 then numerically safe).
// ---------------------------------------------------------------------------
__global__ void __launch_bounds__(128) attn_kernel()
{
    __shared__ unsigned Qh[64][36], Ql[64][36];  // Qh aliased as P-stage after prologue
    __shared__ unsigned Kh[32][36], Kl[32][36];
    __shared__ unsigned Vs[32][72];

    const int h = blockIdx.y, t0 = blockIdx.x * 64;
    const int tid = threadIdx.x;
    const int lane = tid & 31, warp = tid >> 5;
    const int g = lane >> 2, tig = lane & 3;
    const int wq = t0 + warp * 16;

    // Stage Q (scaled), split to bf16 hi/lo pairs. 64x64 floats = 1024 f4.
#pragma unroll
    for (int u = 0; u < 8; u++) {
        int idx = tid + u * 128;
        int r = idx >> 4, kp = (idx & 15) * 2;
        float4 v = *(const float4*)(g_q + (size_t)(t0 + r) * DM + h * DH + kp * 2);
        unsigned h0, l0, h1, l1;
        split_pair(v.x * 0.125f, v.y * 0.125f, h0, l0);
        split_pair(v.z * 0.125f, v.w * 0.125f, h1, l1);
        Qh[r][kp] = h0; Ql[r][kp] = l0;
        Qh[r][kp + 1] = h1; Ql[r][kp + 1] = l1;
    }
    __syncthreads();

    // Q fragments: A(m16 x k16) per kstep, 4 ksteps cover DH=64
    unsigned qh[4][4], ql[4][4];
    const int rA = warp * 16 + g;
#pragma unroll
    for (int ks = 0; ks < 4; ks++) {
        qh[ks][0] = Qh[rA][ks * 8 + tig];     qh[ks][1] = Qh[rA + 8][ks * 8 + tig];
        qh[ks][2] = Qh[rA][ks * 8 + tig + 4]; qh[ks][3] = Qh[rA + 8][ks * 8 + tig + 4];
        ql[ks][0] = Ql[rA][ks * 8 + tig];     ql[ks][1] = Ql[rA + 8][ks * 8 + tig];
        ql[ks][2] = Ql[rA][ks * 8 + tig + 4]; ql[ks][3] = Ql[rA + 8][ks * 8 + tig + 4];
    }
    __syncwarp();  // all lanes' q-frag reads done before Qh is reused as P-stage

    float o[8][4];
#pragma unroll
    for (int nt = 0; nt < 8; nt++)
#pragma unroll
        for (int e = 0; e < 4; e++) o[nt][e] = 0.0f;
    float m0 = -1e30f, m1 = -1e30f, l0 = 0.0f, l1 = 0.0f;

    const int jlo = max(0, t0 - WIN);
    const int jtop_w = ((wq + 15) >> 5) << 5;  // chunk containing this warp's diagonal

    for (int jc = t0 + 32; jc >= jlo; jc -= 32) {
        __syncthreads();  // previous chunk's smem reads complete
        // Stage K (bf16 split pairs) and V (tf32): 32x64 each
#pragma unroll
        for (int u = 0; u < 4; u++) {
            int idx = tid + u * 128;
            int r = idx >> 4, kp = (idx & 15) * 2;
            float4 kv = *(const float4*)(g_k + (size_t)(jc + r) * DM + h * DH + kp * 2);
            unsigned h0, lv0, h1, lv1;
            split_pair(kv.x, kv.y, h0, lv0);
            split_pair(kv.z, kv.w, h1, lv1);
            Kh[r][kp] = h0; Kl[r][kp] = lv0;
            Kh[r][kp + 1] = h1; Kl[r][kp + 1] = lv1;
            float4 vv = *(const float4*)(g_v + (size_t)(jc + r) * DM + h * DH + kp * 2);
            Vs[r][kp * 2 + 0] = f2tf(vv.x); Vs[r][kp * 2 + 1] = f2tf(vv.y);
            Vs[r][kp * 2 + 2] = f2tf(vv.z); Vs[r][kp * 2 + 3] = f2tf(vv.w);
        }
        __syncthreads();

        if (jc <= jtop_w && jc + 31 + WIN >= wq) {
            // Scores: S(16x32) = Q(16x64) @ K^T, bf16x2
            float s[4][4];
#pragma unroll
            for (int nt = 0; nt < 4; nt++)
#pragma unroll
                for (int e = 0; e < 4; e++) s[nt][e] = 0.0f;
#pragma unroll
            for (int ks = 0; ks < 4; ks++) {
#pragma unroll
                for (int nt = 0; nt < 4; nt++) {
                    unsigned bh[2], bl[2];
                    bh[0] = Kh[nt * 8 + g][ks * 8 + tig];
                    bh[1] = Kh[nt * 8 + g][ks * 8 + tig + 4];
                    bl[0] = Kl[nt * 8 + g][ks * 8 + tig];
                    bl[1] = Kl[nt * 8 + g][ks * 8 + tig + 4];
                    mma_bf(s[nt], qh[ks], bh);
                    mma_bf(s[nt], qh[ks], bl);
                    mma_bf(s[nt], ql[ks], bh);
                }
            }

            // Mask + online softmax (rows r0 = wq+g, r1 = wq+g+8)
            const int r0 = wq + g, r1 = r0 + 8;
            float mx0 = -1e30f, mx1 = -1e30f;
#pragma unroll
            for (int nt = 0; nt < 4; nt++) {
#pragma unroll
                for (int e = 0; e < 2; e++) {
                    int j = jc + nt * 8 + 2 * tig + e;
                    if (j > r0 || j + WIN < r0) s[nt][e] = -1e30f;
                    if (j > r1 || j + WIN < r1) s[nt][2 + e] = -1e30f;
                    mx0 = fmaxf(mx0, s[nt][e]);
                    mx1 = fmaxf(mx1, s[nt][2 + e]);
                }
            }
            mx0 = fmaxf(mx0, __shfl_xor_sync(0xffffffffu, mx0, 1));
            mx0 = fmaxf(mx0, __shfl_xor_sync(0xffffffffu, mx0, 2));
            mx1 = fmaxf(mx1, __shfl_xor_sync(0xffffffffu, mx1, 1));
            mx1 = fmaxf(mx1, __shfl_xor_sync(0xffffffffu, mx1, 2));
            float mn0 = fmaxf(m0, mx0), mn1 = fmaxf(m1, mx1);
            float c0 = __expf(m0 - mn0), c1 = __expf(m1 - mn1);
            m0 = mn0; m1 = mn1;
            l0 *= c0; l1 *= c1;
#pragma unroll
            for (int nt = 0; nt < 8; nt++) {
                o[nt][0] *= c0; o[nt][1] *= c0;
                o[nt][2] *= c1; o[nt][3] *= c1;
            }
            float ls0 = 0.0f, ls1 = 0.0f;
#pragma unroll
            for (int nt = 0; nt < 4; nt++) {
                float p00 = __expf(s[nt][0] - mn0), p01 = __expf(s[nt][1] - mn0);
                float p10 = __expf(s[nt][2] - mn1), p11 = __expf(s[nt][3] - mn1);
                ls0 += p00 + p01; ls1 += p10 + p11;
                uint2 w0; w0.x = f2tf(p00); w0.y = f2tf(p01);
                uint2 w1; w1.x = f2tf(p10); w1.y = f2tf(p11);
                *(uint2*)&Qh[rA][nt * 8 + 2 * tig] = w0;          // P-stage (tf32)
                *(uint2*)&Qh[rA + 8][nt * 8 + 2 * tig] = w1;
            }
            ls0 += __shfl_xor_sync(0xffffffffu, ls0, 1);
            ls0 += __shfl_xor_sync(0xffffffffu, ls0, 2);
            ls1 += __shfl_xor_sync(0xffffffffu, ls1, 1);
            ls1 += __shfl_xor_sync(0xffffffffu, ls1, 2);
            l0 += ls0; l1 += ls1;
            __syncwarp();

            // O += P(16x32) @ V(32x64), tf32
#pragma unroll
            for (int ks2 = 0; ks2 < 4; ks2++) {
                unsigned pa[4];
                pa[0] = Qh[rA][ks2 * 8 + tig];
                pa[1] = Qh[rA + 8][ks2 * 8 + tig];
                pa[2] = Qh[rA][ks2 * 8 + tig + 4];
                pa[3] = Qh[rA + 8][ks2 * 8 + tig + 4];
#pragma unroll
                for (int nt = 0; nt < 8; nt++) {
                    unsigned vb[2];
                    vb[0] = Vs[ks2 * 8 + tig][nt * 8 + g];
                    vb[1] = Vs[ks2 * 8 + tig + 4][nt * 8 + g];
                    mma_tf(o[nt], pa, vb);
                }
            }
        }
    }

    // Epilogue: normalize and store
    const float inv0 = 1.0f / l0, inv1 = 1.0f / l1;
#pragma unroll
    for (int nt = 0; nt < 8; nt++) {
        int col = h * DH + nt * 8 + 2 * tig;
        *(float2*)(g_attn + (size_t)(wq + g) * DM + col) =
            make_float2(o[nt][0] * inv0, o[nt][1] * inv0);
        *(float2*)(g_attn + (size_t)(wq + g + 8) * DM + col) =
            make_float2(o[nt][2] * inv1, o[nt][3] * inv1);
    }
}

// ---------------------------------------------------------------------------
extern "C" void kernel_launch(void* const* d_in, const int* in_sizes, int n_in,
                              void* d_out, int out_size)
{
    const float* x  = (const float*)d_in[0];
    const float* Wq = (const float*)d_in[1];
    const float* Wk = (const float*)d_in[2];
    const float* Wv = (const float*)d_in[3];
    const float* Wo = (const float*)d_in[4];
    float* out = (float*)d_out;

    float *q, *k, *v, *attn;
    cudaGetSymbolAddress((void**)&q,    g_q);
    cudaGetSymbolAddress((void**)&k,    g_k);
    cudaGetSymbolAddress((void**)&v,    g_v);
    cudaGetSymbolAddress((void**)&attn, g_attn);

    dim3 ggrid(DM / 128, SEQ / 128);  // (8, 32)
    gemm_bf16x2<<<ggrid, 256>>>(x, Wq, q, SEQ, DM, DM);
    gemm_bf16x2<<<ggrid, 256>>>(x, Wk, k, SEQ, DM, DM);
    gemm_bf16x2<<<ggrid, 256>>>(x, Wv, v, SEQ, DM, DM);

    attn_kernel<<<dim3(SEQ / 64, NH), 128>>>();

    gemm_bf16x2<<<ggrid, 256>>>(attn, Wo, out, SEQ, DM, DM);
}